// round 11
// baseline (speedup 1.0000x reference)
#include <cuda_runtime.h>
#include <cuda_bf16.h>
#include <cstdint>

#define EMB 300
#define HSTR 304
#define BATCH 256
#define NNODE 64

// ---------------- scratch (static device memory; zero-initialized) -----------
__device__ float g_h[2 * BATCH * NNODE * HSTR];
__device__ float g_t[2 * BATCH * NNODE * HSTR];
__device__ __align__(16) __nv_bfloat16 g_hbhi[2 * BATCH * NNODE * 320];
__device__ __align__(16) __nv_bfloat16 g_hblo[2 * BATCH * NNODE * 320];
__device__ __align__(16) __nv_bfloat16 g_WencK[3 * 2 * 320 * 320]; // [rel][hi/lo][f][k]
__device__ __align__(16) __nv_bfloat16 g_W0B[2 * 600 * 1824];      // [hi/lo][f][k]
__device__ __align__(16) __nv_bfloat16 g_W12B[2 * 2 * 600 * 640];  // [ly][hi/lo][f][k]
__device__ __align__(16) __nv_bfloat16 g_xb[2 * 256 * 1824];       // [hi/lo][b][k]
__device__ __align__(16) __nv_bfloat16 g_y0b[2 * 256 * 640];
__device__ __align__(16) __nv_bfloat16 g_y1b[2 * 256 * 640];
__device__ __align__(16) float g_zero[8];                          // stays zero
__device__ float g_rep[2 * BATCH * EMB];
__device__ float g_acc0[19 * BATCH * 600];
__device__ float g_acc1[10 * BATCH * 600];
__device__ float g_acc2[10 * BATCH * 600];
__device__ int   g_rows[9][22016];
__device__ int   g_cnt[9];

// ---------------- helpers -----------------------------------------------------
__device__ __forceinline__ uint32_t s2u(const void* p) {
    return (uint32_t)__cvta_generic_to_shared(p);
}
__device__ __forceinline__ void cpa16(uint32_t s, const void* g) {
    asm volatile("cp.async.cg.shared.global [%0],[%1],16;" :: "r"(s), "l"(g));
}
__device__ __forceinline__ void cpa_commit() { asm volatile("cp.async.commit_group;"); }
template <int N> __device__ __forceinline__ void cpa_wait() {
    asm volatile("cp.async.wait_group %0;" :: "n"(N));
}
__device__ __forceinline__ void ldsm4(uint32_t* r, uint32_t a) {
    asm volatile("ldmatrix.sync.aligned.m8n8.x4.shared.b16 {%0,%1,%2,%3},[%4];"
        : "=r"(r[0]), "=r"(r[1]), "=r"(r[2]), "=r"(r[3]) : "r"(a));
}
__device__ __forceinline__ void mma_bf16(float* c, const uint32_t* a, const uint32_t* b) {
    asm volatile(
        "mma.sync.aligned.m16n8k16.row.col.f32.bf16.bf16.f32 "
        "{%0,%1,%2,%3},{%4,%5,%6,%7},{%8,%9},{%0,%1,%2,%3};"
        : "+f"(c[0]), "+f"(c[1]), "+f"(c[2]), "+f"(c[3])
        : "r"(a[0]), "r"(a[1]), "r"(a[2]), "r"(a[3]), "r"(b[0]), "r"(b[1]));
}

// ---------------- 1. unified weight conversion (Wenc + W0 + W1/W2) -------------
__global__ void wtrans_fused(const float* __restrict__ Wenc, const float* __restrict__ W0,
                             const float* __restrict__ W1, const float* __restrict__ W2) {
    int gi = blockIdx.x * 256 + threadIdx.x;
    if (gi < 9) g_cnt[gi] = 0;
    if (gi < 270000) {                  // Wenc: 3 x 300 x 300
        int rel = gi / 90000;
        int r2 = gi - rel * 90000;
        int f = r2 / 300, k = r2 - f * 300;
        float v = Wenc[gi];
        __nv_bfloat16 hi = __float2bfloat16(v);
        __nv_bfloat16 lo = __float2bfloat16(v - __bfloat162float(hi));
        g_WencK[((size_t)(rel * 2 + 0) * 320 + f) * 320 + k] = hi;
        g_WencK[((size_t)(rel * 2 + 1) * 320 + f) * 320 + k] = lo;
        return;
    }
    gi -= 270000;
    if (gi < 1080000) {                 // W0: 600 x 1800
        int f = gi / 1800, k = gi - f * 1800;
        float v = W0[gi];
        __nv_bfloat16 hi = __float2bfloat16(v);
        __nv_bfloat16 lo = __float2bfloat16(v - __bfloat162float(hi));
        g_W0B[(size_t)f * 1824 + k] = hi;
        g_W0B[(size_t)(600 + f) * 1824 + k] = lo;
        return;
    }
    gi -= 1080000;
    if (gi >= 720000) return;           // W1/W2: 600 x 600 each
    int ly = gi / 360000;
    int r2 = gi - ly * 360000;
    int f = r2 / 600, k = r2 - f * 600;
    float v = (ly ? W2 : W1)[r2];
    __nv_bfloat16 hi = __float2bfloat16(v);
    __nv_bfloat16 lo = __float2bfloat16(v - __bfloat162float(hi));
    size_t base = (size_t)ly * 2 * 600 * 640;
    g_W12B[base + (size_t)f * 640 + k] = hi;
    g_W12B[base + (size_t)(600 + f) * 640 + k] = lo;
}

// ---------------- 2. embeddings: smem-staged, block-uniform barriers ------------
__global__ void __launch_bounds__(320) embed_kernel(
        const int* __restrict__ px, const int* __restrict__ hx,
        const int* __restrict__ pwi, const int* __restrict__ hwi,
        const float* __restrict__ E) {
    __shared__ float stage[32][300];
    __shared__ int sx[64], swi[64];
    int tid = threadIdx.x;
    int b = blockIdx.x & 255;
    int tree = blockIdx.x >> 8;
    const int* x  = (tree ? hx : px) + b * 64;
    const int* wi = (tree ? hwi : pwi) + b * 64;
    if (tid < 64) { sx[tid] = x[tid]; swi[tid] = wi[tid]; }
    __syncthreads();
    size_t row0 = (size_t)(tree * BATCH + b) * NNODE;
    float* hb = g_h + row0 * HSTR;
    __nv_bfloat16* mhi = g_hbhi + row0 * 320;
    __nv_bfloat16* mlo = g_hblo + row0 * 320;
    bool active = (tid < 300);

    // pad lanes: zero hb cols 300..303 and mirror cols 300..319 (no early return)
    if (!active) {
        int pc = tid - 300;             // 0..19
        __nv_bfloat16 z = __float2bfloat16(0.f);
        for (int n = 0; n < 64; n++) {
            if (pc < 4) hb[n * HSTR + 300 + pc] = 0.f;
            mhi[n * 320 + tid] = z;
            mlo[n * 320 + tid] = z;
        }
    }

    float rep = 0.f;
#pragma unroll
    for (int pass = 0; pass < 2; pass++) {
        if (pass) __syncthreads();      // prior pass fully consumed (ALL threads)
        if (active) {
            int r0 = pass * 32;
#pragma unroll 4
            for (int r = 0; r < 32; r++) {
                float v = __ldg(&E[(size_t)sx[r0 + r] * EMB + tid]);
                stage[r][tid] = v;
                rep += v;
            }
        }
        __syncthreads();                // staged (ALL threads)
        if (active) {
            for (int n = 0; n < 64; n++) {
                int w = swi[n];
                float v;
                if (w < 0) { if (pass) continue; v = 1.0f; }
                else {
                    if ((w >> 5) != pass) continue;
                    v = stage[w & 31][tid];
                }
                hb[n * HSTR + tid] = v;
                __nv_bfloat16 hi = __float2bfloat16(v);
                mhi[n * 320 + tid] = hi;
                mlo[n * 320 + tid] = __float2bfloat16(v - __bfloat162float(hi));
            }
        }
    }
    if (active) g_rep[((size_t)tree * BATCH + b) * EMB + tid] = rep;
}

// ---------------- 3. compaction per (level, rel) --------------------------------
__global__ void compact_kernel(const int* __restrict__ prel, const int* __restrict__ hrel) {
    __shared__ unsigned ball[64];
    __shared__ int pref[64];
    __shared__ int sbase;
    int tid = threadIdx.x, lane = tid & 31, wid = tid >> 5;
    int cb = blockIdx.x;
    int li = cb % 9, chunk = cb / 9;
    int l = li / 3, r = li % 3;
    int n0, nc;
    if (l == 0)      { n0 = 1;  nc = 4;  }
    else if (l == 1) { n0 = 5;  nc = 16; }
    else             { n0 = 21; nc = 43; }
    int total = 512 * nc;
    int base = chunk * 2048;
    if (base >= total) return;
#pragma unroll
    for (int it = 0; it < 8; it++) {
        int i = base + it * 256 + tid;
        int flag = 0;
        if (i < total) {
            int tb = i / nc;
            int n = n0 + (i - tb * nc);
            int tree = tb >> 8, b = tb & 255;
            flag = ((tree ? hrel : prel)[b * 64 + n] == r);
        }
        unsigned m = __ballot_sync(0xffffffffu, flag);
        if (lane == 0) ball[wid * 8 + it] = m;
    }
    __syncthreads();
    if (tid == 0) {
        int run = 0;
        for (int s = 0; s < 64; s++) { pref[s] = run; run += __popc(ball[s]); }
        sbase = atomicAdd(&g_cnt[li], run);
    }
    __syncthreads();
#pragma unroll
    for (int it = 0; it < 8; it++) {
        int i = base + it * 256 + tid;
        int flag = 0, v = 0;
        if (i < total) {
            int tb = i / nc;
            int n = n0 + (i - tb * nc);
            int tree = tb >> 8, b = tb & 255;
            flag = ((tree ? hrel : prel)[b * 64 + n] == r);
            v = (tb << 6) | n;
        }
        unsigned m = ball[wid * 8 + it];
        int within = __popc(m & ((1u << lane) - 1));
        if (flag) g_rows[li][sbase + pref[wid * 8 + it] + within] = v;
    }
}

// ---------------- 4. tree GEMM: 64x160 tile, warp 16x80, 3xBF16 -----------------
// static smem: A[buf][hl][64][48B]=12288, B[buf][hl][160][48B]=30720 -> 43008
__global__ void __launch_bounds__(256, 3) tree_mma(int l) {
    __shared__ __align__(16) char smem[43008];
    __shared__ int meta[64];
    int rel = blockIdx.z;
    int li = l * 3 + rel;
    int cnt = g_cnt[li];
    int row0 = blockIdx.x * 64;
    if (row0 >= cnt) return;
    int fs = blockIdx.y * 160;

    uint32_t sb = s2u(smem);
    int tid = threadIdx.x, lane = tid & 31, warp = tid >> 5;
    int warp_m = warp >> 1, warp_n = warp & 1;
    if (tid < 64) {
        int rr = row0 + tid;
        meta[tid] = (rr < cnt) ? g_rows[li][rr] : -1;
    }
    __syncthreads();

    uint32_t aoff = (uint32_t)((warp_m * 16 + (lane & 15)) * 48 + (lane >> 4) * 16);
    uint32_t boff = (uint32_t)((warp_n * 80 + ((lane >> 4) << 3) + (lane & 7)) * 48
                               + ((lane >> 3) & 1) * 16);

    auto fill = [&](int c, int buf) {
        int k0 = c * 16;
        for (int i = tid; i < 896; i += 256) {
            if (i < 256) {
                int hl = i >> 7, j = i & 127, m = j >> 1, half = j & 1;
                int mm = meta[m];
                const void* src = (mm < 0) ? (const void*)g_zero
                    : (const void*)((hl ? g_hblo : g_hbhi) + (size_t)mm * 320 + k0 + half * 8);
                cpa16(sb + (uint32_t)(buf * 6144 + hl * 3072 + m * 48 + half * 16), src);
            } else {
                int i2 = i - 256;
                int hl = (i2 >= 320);
                int j = i2 - (hl ? 320 : 0);
                int n = j >> 1, half = j & 1;
                const __nv_bfloat16* src =
                    g_WencK + ((size_t)(rel * 2 + hl) * 320 + fs + n) * 320 + k0 + half * 8;
                cpa16(sb + (uint32_t)(12288 + buf * 15360 + hl * 7680 + n * 48 + half * 16), src);
            }
        }
        cpa_commit();
    };

    float C[10][4];
#pragma unroll
    for (int ni = 0; ni < 10; ni++)
#pragma unroll
        for (int q = 0; q < 4; q++) C[ni][q] = 0.f;

    fill(0, 0);
    for (int t = 0; t < 20; t++) {
        int buf = t & 1;
        if (t < 19) { fill(t + 1, buf ^ 1); cpa_wait<1>(); }
        else        { cpa_wait<0>(); }
        __syncthreads();

        uint32_t abase = sb + (uint32_t)(buf * 6144) + aoff;
        uint32_t Ah[4], Al[4];
        ldsm4(Ah, abase);
        ldsm4(Al, abase + 3072);
        uint32_t bbase = sb + (uint32_t)(12288 + buf * 15360) + boff;
#pragma unroll
        for (int pair = 0; pair < 5; pair++) {
            uint32_t Bh4[4], Bl4[4];
            ldsm4(Bh4, bbase + pair * 768);
            ldsm4(Bl4, bbase + 7680 + pair * 768);
#pragma unroll
            for (int sub = 0; sub < 2; sub++) {
                int ni = pair * 2 + sub;
                mma_bf16(C[ni], Ah, Bh4 + sub * 2);
                mma_bf16(C[ni], Ah, Bl4 + sub * 2);
                mma_bf16(C[ni], Al, Bh4 + sub * 2);
            }
        }
        __syncthreads();
    }

    int r0 = warp_m * 16 + (lane >> 2);
    int mmA = meta[r0], mmB = meta[r0 + 8];
#pragma unroll
    for (int ni = 0; ni < 10; ni++) {
        int f = fs + warp_n * 80 + ni * 8 + (lane & 3) * 2;
        if (f < 300) {
            if (mmA >= 0)
                *(float2*)(g_t + (size_t)mmA * HSTR + f) = make_float2(C[ni][0], C[ni][1]);
            if (mmB >= 0)
                *(float2*)(g_t + (size_t)mmB * HSTR + f) = make_float2(C[ni][2], C[ni][3]);
        }
    }
}

// ---------------- 5. MLP GEMM: same tiling, k-split slabs ------------------------
__global__ void __launch_bounds__(256, 3) fc_mma(int sel, int kpad, int nt) {
    __shared__ __align__(16) char smem[43008];
    uint32_t sb = s2u(smem);
    int m0 = blockIdx.x * 64;
    int fs = blockIdx.y * 160;
    int z  = blockIdx.z;
    int kbeg = z * nt * 16;

    const __nv_bfloat16 *Ahi, *Alo, *WB;
    float* acc;
    if (sel == 0)      { Ahi = g_xb;  Alo = g_xb  + 256 * 1824; WB = g_W0B;  acc = g_acc0; }
    else if (sel == 1) { Ahi = g_y0b; Alo = g_y0b + 256 * 640;  WB = g_W12B; acc = g_acc1; }
    else               { Ahi = g_y1b; Alo = g_y1b + 256 * 640;
                         WB = g_W12B + 2 * 600 * 640;            acc = g_acc2; }

    int tid = threadIdx.x, lane = tid & 31, warp = tid >> 5;
    int warp_m = warp >> 1, warp_n = warp & 1;
    uint32_t aoff = (uint32_t)((warp_m * 16 + (lane & 15)) * 48 + (lane >> 4) * 16);
    uint32_t boff = (uint32_t)((warp_n * 80 + ((lane >> 4) << 3) + (lane & 7)) * 48
                               + ((lane >> 3) & 1) * 16);

    auto fill = [&](int c, int buf) {
        int k0 = kbeg + c * 16;
        for (int i = tid; i < 896; i += 256) {
            if (i < 256) {
                int hl = i >> 7, j = i & 127, m = j >> 1, half = j & 1;
                const __nv_bfloat16* src =
                    (hl ? Alo : Ahi) + (size_t)(m0 + m) * kpad + k0 + half * 8;
                cpa16(sb + (uint32_t)(buf * 6144 + hl * 3072 + m * 48 + half * 16), src);
            } else {
                int i2 = i - 256;
                int hl = (i2 >= 320);
                int j = i2 - (hl ? 320 : 0);
                int n = j >> 1, half = j & 1;
                int f = fs + n;
                const void* src = (f < 600)
                    ? (const void*)(WB + ((size_t)hl * 600 + f) * kpad + k0 + half * 8)
                    : (const void*)g_zero;
                cpa16(sb + (uint32_t)(12288 + buf * 15360 + hl * 7680 + n * 48 + half * 16), src);
            }
        }
        cpa_commit();
    };

    float C[10][4];
#pragma unroll
    for (int ni = 0; ni < 10; ni++)
#pragma unroll
        for (int q = 0; q < 4; q++) C[ni][q] = 0.f;

    fill(0, 0);
    for (int t = 0; t < nt; t++) {
        int buf = t & 1;
        if (t < nt - 1) { fill(t + 1, buf ^ 1); cpa_wait<1>(); }
        else            { cpa_wait<0>(); }
        __syncthreads();

        uint32_t abase = sb + (uint32_t)(buf * 6144) + aoff;
        uint32_t Ah[4], Al[4];
        ldsm4(Ah, abase);
        ldsm4(Al, abase + 3072);
        uint32_t bbase = sb + (uint32_t)(12288 + buf * 15360) + boff;
#pragma unroll
        for (int pair = 0; pair < 5; pair++) {
            uint32_t Bh4[4], Bl4[4];
            ldsm4(Bh4, bbase + pair * 768);
            ldsm4(Bl4, bbase + 7680 + pair * 768);
#pragma unroll
            for (int sub = 0; sub < 2; sub++) {
                int ni = pair * 2 + sub;
                mma_bf16(C[ni], Ah, Bh4 + sub * 2);
                mma_bf16(C[ni], Ah, Bl4 + sub * 2);
                mma_bf16(C[ni], Al, Bh4 + sub * 2);
            }
        }
        __syncthreads();
    }

    int row = m0 + warp_m * 16 + (lane >> 2);
#pragma unroll
    for (int ni = 0; ni < 10; ni++) {
        int f = fs + warp_n * 80 + ni * 8 + (lane & 3) * 2;
        if (f < 600) {
            *(float2*)(acc + (size_t)z * 153600 + (size_t)row * 600 + f) =
                make_float2(C[ni][0], C[ni][1]);
            *(float2*)(acc + (size_t)z * 153600 + (size_t)(row + 8) * 600 + f) =
                make_float2(C[ni][2], C[ni][3]);
        }
    }
}

// ---------------- 6. combine (float4) + bf16 mirror refresh ---------------------
__global__ void update_kernel(const int* __restrict__ prel, const int* __restrict__ hrel,
                              int plo) {
    int p = plo + blockIdx.x;
    int b = blockIdx.y, tree = blockIdx.z;
    int e4 = threadIdx.x;
    if (e4 >= 76) return;
    const int* rel = (tree ? hrel : prel) + b * 64;
    size_t rbase = (size_t)(tree * BATCH + b) * NNODE;
    size_t base = rbase * HSTR;
    const float4* hb = (const float4*)(g_h + base);
    const float4* tb = (const float4*)(g_t + base);
    int c0 = 4 * p + 1;
    int c1 = 4 * p + 4; if (c1 > 63) c1 = 63;
    float4 s = make_float4(0.f, 0.f, 0.f, 0.f);
#pragma unroll
    for (int c = c0; c <= c1; c++) {
        if (c > 63) break;
        unsigned rid = (unsigned)rel[c];
        const float4* src = (rid <= 2u) ? tb : hb;
        float4 v = src[c * 76 + e4];
        s.x += v.x; s.y += v.y; s.z += v.z; s.w += v.w;
    }
    float cntf = (float)(c1 - c0 + 1);
    float4 hp = hb[p * 76 + e4];
    float4 o;
    o.x = fmaxf(hp.x * (s.x / cntf), 0.f);
    o.y = fmaxf(hp.y * (s.y / cntf), 0.f);
    o.z = fmaxf(hp.z * (s.z / cntf), 0.f);
    o.w = fmaxf(hp.w * (s.w / cntf), 0.f);
    ((float4*)(g_h + base))[p * 76 + e4] = o;
    __nv_bfloat16* mhi = g_hbhi + (rbase + p) * 320 + 4 * e4;
    __nv_bfloat16* mlo = g_hblo + (rbase + p) * 320 + 4 * e4;
    float vv[4] = {o.x, o.y, o.z, o.w};
#pragma unroll
    for (int q = 0; q < 4; q++) {
        __nv_bfloat16 hi = __float2bfloat16(vv[q]);
        mhi[q] = hi;
        mlo[q] = __float2bfloat16(vv[q] - __bfloat162float(hi));
    }
}

// ---------------- 7. fused root update + MLP input (bf16 hi/lo planes) ----------
__global__ void update1_buildx(const int* __restrict__ prel, const int* __restrict__ hrel) {
    int b = blockIdx.x;
    int e = threadIdx.x;
    __shared__ float root[2][300];
#pragma unroll
    for (int tree = 0; tree < 2; tree++) {
        if (e < 300) {
            const int* rel = (tree ? hrel : prel) + b * 64;
            size_t base = ((size_t)(tree * BATCH + b) * NNODE) * HSTR;
            const float* hb = g_h + base;
            const float* tb = g_t + base;
            float s = 0.f;
#pragma unroll
            for (int c = 1; c <= 4; c++) {
                unsigned rid = (unsigned)rel[c];
                s += (rid <= 2u) ? tb[c * HSTR + e] : hb[c * HSTR + e];
            }
            float v = hb[e] * (s * 0.25f);
            root[tree][e] = fmaxf(v, 0.f);
        }
    }
    __syncthreads();
    if (e >= 300) return;
    float pr = g_rep[b * EMB + e];
    float hr = g_rep[(BATCH + b) * EMB + e];
    float ps = root[0][e], hs = root[1][e];
    float vals[6] = {pr, hr, pr - hr, pr * hr, ps - hs, ps * hs};
    __nv_bfloat16* xh = g_xb + (size_t)b * 1824;
    __nv_bfloat16* xl = g_xb + 256 * 1824 + (size_t)b * 1824;
#pragma unroll
    for (int i = 0; i < 6; i++) {
        int col = i * 300 + e;
        __nv_bfloat16 hi = __float2bfloat16(vals[i]);
        xh[col] = hi;
        xl[col] = __float2bfloat16(vals[i] - __bfloat162float(hi));
    }
}

// ---------------- 8. reduce k-split slabs + bias + relu -> bf16 planes ----------
__global__ void bias_relu_kernel(const float* __restrict__ bias, int sel, int nz) {
    int b = blockIdx.x, n = threadIdx.x;
    const float* acc = (sel == 0) ? g_acc0 : g_acc1;
    float s = bias[n];
    for (int z = 0; z < nz; z++) s += acc[(size_t)z * BATCH * 600 + b * 600 + n];
    float v = s > 0.f ? s : 0.f;
    __nv_bfloat16* yh = (sel == 0) ? g_y0b : g_y1b;
    __nv_bfloat16 hi = __float2bfloat16(v);
    yh[(size_t)b * 640 + n] = hi;
    yh[256 * 640 + (size_t)b * 640 + n] = __float2bfloat16(v - __bfloat162float(hi));
}

// ---------------- 9. fused layer-2 reduce + bias + relu + output ----------------
__global__ void bias2_out(const float* __restrict__ bias, const float* __restrict__ Wout,
                          const float* __restrict__ bout, float* __restrict__ out) {
    int b = blockIdx.x, n = threadIdx.x;
    __shared__ float sy[600];
    if (n < 600) {
        float s = bias[n];
        for (int z = 0; z < 10; z++) s += g_acc2[(size_t)z * BATCH * 600 + b * 600 + n];
        sy[n] = s > 0.f ? s : 0.f;
    }
    __syncthreads();
    int w = n >> 5, lane = n & 31;
    if (w >= 3) return;
    float s = 0.f;
    for (int k = lane; k < 600; k += 32)
        s += sy[k] * Wout[w * 600 + k];
    for (int o = 16; o; o >>= 1) s += __shfl_down_sync(0xffffffffu, s, o);
    if (lane == 0) out[b * 3 + w] = s + bout[w];
}

// ---------------- launch ----------------------------------------------------------
extern "C" void kernel_launch(void* const* d_in, const int* in_sizes, int n_in,
                              void* d_out, int out_size) {
    const int*   px   = (const int*)d_in[0];
    const int*   hx   = (const int*)d_in[1];
    const int*   pwi  = (const int*)d_in[2];
    const int*   prel = (const int*)d_in[3];
    const int*   hwi  = (const int*)d_in[4];
    const int*   hrel = (const int*)d_in[5];
    const float* E    = (const float*)d_in[8];
    const float* Wenc = (const float*)d_in[9];
    const float* W0w  = (const float*)d_in[10];
    const float* W0b  = (const float*)d_in[11];
    const float* W1w  = (const float*)d_in[12];
    const float* W1b  = (const float*)d_in[13];
    const float* W2w  = (const float*)d_in[14];
    const float* W2b  = (const float*)d_in[15];
    const float* Wow  = (const float*)d_in[16];
    const float* Wob  = (const float*)d_in[17];
    float* out = (float*)d_out;

    wtrans_fused<<<8086, 256>>>(Wenc, W0w, W1w, W2w);                     // 1 (+zero g_cnt)
    embed_kernel<<<512, 320>>>(px, hx, pwi, hwi, E);                      // 2
    compact_kernel<<<99, 256>>>(prel, hrel);                              // 3

    tree_mma<<<dim3(344, 2, 3), 256>>>(2);                                // 4
    update_kernel<<<dim3(11, 256, 2), 96>>>(prel, hrel, 5);               // 5
    tree_mma<<<dim3(128, 2, 3), 256>>>(1);                                // 6 <- profiled
    update_kernel<<<dim3(4, 256, 2), 96>>>(prel, hrel, 1);                // 7
    tree_mma<<<dim3(32, 2, 3), 256>>>(0);                                 // 8
    update1_buildx<<<256, 320>>>(prel, hrel);                             // 9

    fc_mma<<<dim3(4, 4, 19), 256>>>(0, 1824, 6);                          // 10
    bias_relu_kernel<<<256, 600>>>(W0b, 0, 19);                           // 11
    fc_mma<<<dim3(4, 4, 10), 256>>>(1, 640, 4);                           // 12
    bias_relu_kernel<<<256, 600>>>(W1b, 1, 10);                           // 13
    fc_mma<<<dim3(4, 4, 10), 256>>>(2, 640, 4);                           // 14
    bias2_out<<<256, 608>>>(W2b, Wow, Wob, out);                          // 15
}

// round 12
// speedup vs baseline: 1.0867x; 1.0867x over previous
#include <cuda_runtime.h>
#include <cuda_bf16.h>
#include <cstdint>

#define EMB 300
#define HSTR 304
#define BATCH 256
#define NNODE 64

// ---------------- scratch (static device memory; zero-initialized) -----------
__device__ float g_h[2 * BATCH * NNODE * HSTR];
__device__ float g_t[2 * BATCH * NNODE * HSTR];
__device__ __align__(16) __nv_bfloat16 g_hbhi[2 * BATCH * NNODE * 320];
__device__ __align__(16) __nv_bfloat16 g_hblo[2 * BATCH * NNODE * 320];
__device__ __align__(16) __nv_bfloat16 g_WencK[3 * 2 * 320 * 320]; // [rel][hi/lo][f][k]
__device__ __align__(16) __nv_bfloat16 g_W0B[2 * 600 * 1824];      // [hi/lo][f][k]
__device__ __align__(16) __nv_bfloat16 g_W12B[2 * 2 * 600 * 640];  // [ly][hi/lo][f][k]
__device__ __align__(16) __nv_bfloat16 g_xb[2 * 256 * 1824];       // [hi/lo][b][k]
__device__ __align__(16) __nv_bfloat16 g_y0b[2 * 256 * 640];
__device__ __align__(16) __nv_bfloat16 g_y1b[2 * 256 * 640];
__device__ __align__(16) float g_zero[8];                          // stays zero
__device__ float g_rep2[2][2 * BATCH * EMB];                       // rep partials
__device__ float g_acc0[19 * BATCH * 600];
__device__ float g_acc1[10 * BATCH * 600];
__device__ float g_acc2[10 * BATCH * 600];
__device__ int   g_rows[9][22016];
__device__ int   g_cnt[9];

// ---------------- helpers -----------------------------------------------------
__device__ __forceinline__ uint32_t s2u(const void* p) {
    return (uint32_t)__cvta_generic_to_shared(p);
}
__device__ __forceinline__ void cpa16(uint32_t s, const void* g) {
    asm volatile("cp.async.cg.shared.global [%0],[%1],16;" :: "r"(s), "l"(g));
}
__device__ __forceinline__ void cpa_commit() { asm volatile("cp.async.commit_group;"); }
template <int N> __device__ __forceinline__ void cpa_wait() {
    asm volatile("cp.async.wait_group %0;" :: "n"(N));
}
__device__ __forceinline__ void ldsm4(uint32_t* r, uint32_t a) {
    asm volatile("ldmatrix.sync.aligned.m8n8.x4.shared.b16 {%0,%1,%2,%3},[%4];"
        : "=r"(r[0]), "=r"(r[1]), "=r"(r[2]), "=r"(r[3]) : "r"(a));
}
__device__ __forceinline__ void mma_bf16(float* c, const uint32_t* a, const uint32_t* b) {
    asm volatile(
        "mma.sync.aligned.m16n8k16.row.col.f32.bf16.bf16.f32 "
        "{%0,%1,%2,%3},{%4,%5,%6,%7},{%8,%9},{%0,%1,%2,%3};"
        : "+f"(c[0]), "+f"(c[1]), "+f"(c[2]), "+f"(c[3])
        : "r"(a[0]), "r"(a[1]), "r"(a[2]), "r"(a[3]), "r"(b[0]), "r"(b[1]));
}

// ---------------- 1. unified weight conversion (Wenc + W0 + W1/W2) -------------
__global__ void wtrans_fused(const float* __restrict__ Wenc, const float* __restrict__ W0,
                             const float* __restrict__ W1, const float* __restrict__ W2) {
    int gi = blockIdx.x * 256 + threadIdx.x;
    if (gi < 9) g_cnt[gi] = 0;
    if (gi < 270000) {                  // Wenc: 3 x 300 x 300
        int rel = gi / 90000;
        int r2 = gi - rel * 90000;
        int f = r2 / 300, k = r2 - f * 300;
        float v = Wenc[gi];
        __nv_bfloat16 hi = __float2bfloat16(v);
        __nv_bfloat16 lo = __float2bfloat16(v - __bfloat162float(hi));
        g_WencK[((size_t)(rel * 2 + 0) * 320 + f) * 320 + k] = hi;
        g_WencK[((size_t)(rel * 2 + 1) * 320 + f) * 320 + k] = lo;
        return;
    }
    gi -= 270000;
    if (gi < 1080000) {                 // W0: 600 x 1800
        int f = gi / 1800, k = gi - f * 1800;
        float v = W0[gi];
        __nv_bfloat16 hi = __float2bfloat16(v);
        __nv_bfloat16 lo = __float2bfloat16(v - __bfloat162float(hi));
        g_W0B[(size_t)f * 1824 + k] = hi;
        g_W0B[(size_t)(600 + f) * 1824 + k] = lo;
        return;
    }
    gi -= 1080000;
    if (gi >= 720000) return;           // W1/W2: 600 x 600 each
    int ly = gi / 360000;
    int r2 = gi - ly * 360000;
    int f = r2 / 600, k = r2 - f * 600;
    float v = (ly ? W2 : W1)[r2];
    __nv_bfloat16 hi = __float2bfloat16(v);
    __nv_bfloat16 lo = __float2bfloat16(v - __bfloat162float(hi));
    size_t base = (size_t)ly * 2 * 600 * 640;
    g_W12B[base + (size_t)f * 640 + k] = hi;
    g_W12B[base + (size_t)(600 + f) * 640 + k] = lo;
}

// ---------------- 2. embeddings (round-9 proven: split halves) ------------------
__global__ void embed_kernel(const int* __restrict__ px, const int* __restrict__ hx,
                             const int* __restrict__ pwi, const int* __restrict__ hwi,
                             const float* __restrict__ E) {
    __shared__ int sx[64], swi[64];
    int tid = threadIdx.x;
    int half = blockIdx.x & 1;
    int b = (blockIdx.x >> 1) & 255;
    int tree = blockIdx.x >> 9;
    const int* x  = (tree ? hx : px) + b * 64;
    const int* wi = (tree ? hwi : pwi) + b * 64;
    if (tid < 64) { sx[tid] = x[tid]; swi[tid] = wi[tid]; }
    __syncthreads();
    size_t row0 = (size_t)(tree * BATCH + b) * NNODE;
    float* hb = g_h + row0 * HSTR;
    __nv_bfloat16* mhi = g_hbhi + row0 * 320;
    __nv_bfloat16* mlo = g_hblo + row0 * 320;
    int n0 = half * 32;
    if (tid >= 300) {
        __nv_bfloat16 z = __float2bfloat16(0.f);
        for (int n = n0; n < n0 + 32; n++) {
            if (tid < 304) hb[n * HSTR + tid] = 0.f;
            mhi[n * 320 + tid] = z;
            mlo[n * 320 + tid] = z;
        }
        return;
    }
    float rep = 0.f;
#pragma unroll 8
    for (int s = n0; s < n0 + 32; s++) rep += __ldg(&E[(size_t)sx[s] * EMB + tid]);
    g_rep2[half][((size_t)tree * BATCH + b) * EMB + tid] = rep;
    for (int n = n0; n < n0 + 32; n++) {
        int w = swi[n];
        float v = (w < 0) ? 1.0f : __ldg(&E[(size_t)sx[w] * EMB + tid]);
        hb[n * HSTR + tid] = v;
        __nv_bfloat16 hi = __float2bfloat16(v);
        mhi[n * 320 + tid] = hi;
        mlo[n * 320 + tid] = __float2bfloat16(v - __bfloat162float(hi));
    }
}

// ---------------- 3. compaction per (level, rel) --------------------------------
__global__ void compact_kernel(const int* __restrict__ prel, const int* __restrict__ hrel) {
    __shared__ unsigned ball[64];
    __shared__ int pref[64];
    __shared__ int sbase;
    int tid = threadIdx.x, lane = tid & 31, wid = tid >> 5;
    int cb = blockIdx.x;
    int li = cb % 9, chunk = cb / 9;
    int l = li / 3, r = li % 3;
    int n0, nc;
    if (l == 0)      { n0 = 1;  nc = 4;  }
    else if (l == 1) { n0 = 5;  nc = 16; }
    else             { n0 = 21; nc = 43; }
    int total = 512 * nc;
    int base = chunk * 2048;
    if (base >= total) return;
#pragma unroll
    for (int it = 0; it < 8; it++) {
        int i = base + it * 256 + tid;
        int flag = 0;
        if (i < total) {
            int tb = i / nc;
            int n = n0 + (i - tb * nc);
            int tree = tb >> 8, b = tb & 255;
            flag = ((tree ? hrel : prel)[b * 64 + n] == r);
        }
        unsigned m = __ballot_sync(0xffffffffu, flag);
        if (lane == 0) ball[wid * 8 + it] = m;
    }
    __syncthreads();
    if (tid == 0) {
        int run = 0;
        for (int s = 0; s < 64; s++) { pref[s] = run; run += __popc(ball[s]); }
        sbase = atomicAdd(&g_cnt[li], run);
    }
    __syncthreads();
#pragma unroll
    for (int it = 0; it < 8; it++) {
        int i = base + it * 256 + tid;
        int flag = 0, v = 0;
        if (i < total) {
            int tb = i / nc;
            int n = n0 + (i - tb * nc);
            int tree = tb >> 8, b = tb & 255;
            flag = ((tree ? hrel : prel)[b * 64 + n] == r);
            v = (tb << 6) | n;
        }
        unsigned m = ball[wid * 8 + it];
        int within = __popc(m & ((1u << lane) - 1));
        if (flag) g_rows[li][sbase + pref[wid * 8 + it] + within] = v;
    }
}

// ---------------- 4. tree GEMM: 64x160, 3xBF16, TRIPLE-buffered ------------------
// dyn smem: A[3][2][64][48B]=18432, B[3][2][160][48B]=46080 -> 64512
#define TMMA_SMEM 64512
__global__ void __launch_bounds__(256, 3) tree_mma(int l) {
    extern __shared__ __align__(16) char smem[];
    __shared__ int meta[64];
    int rel = blockIdx.z;
    int li = l * 3 + rel;
    int cnt = g_cnt[li];
    int row0 = blockIdx.x * 64;
    if (row0 >= cnt) return;
    int fs = blockIdx.y * 160;

    uint32_t sb = s2u(smem);
    int tid = threadIdx.x, lane = tid & 31, warp = tid >> 5;
    int warp_m = warp >> 1, warp_n = warp & 1;
    if (tid < 64) {
        int rr = row0 + tid;
        meta[tid] = (rr < cnt) ? g_rows[li][rr] : -1;
    }
    __syncthreads();

    uint32_t aoff = (uint32_t)((warp_m * 16 + (lane & 15)) * 48 + (lane >> 4) * 16);
    uint32_t boff = (uint32_t)((warp_n * 80 + ((lane >> 4) << 3) + (lane & 7)) * 48
                               + ((lane >> 3) & 1) * 16);

    auto fill = [&](int c, int buf) {
        int k0 = c * 16;
        for (int i = tid; i < 896; i += 256) {
            if (i < 256) {
                int hl = i >> 7, j = i & 127, m = j >> 1, half = j & 1;
                int mm = meta[m];
                const void* src = (mm < 0) ? (const void*)g_zero
                    : (const void*)((hl ? g_hblo : g_hbhi) + (size_t)mm * 320 + k0 + half * 8);
                cpa16(sb + (uint32_t)(buf * 6144 + hl * 3072 + m * 48 + half * 16), src);
            } else {
                int i2 = i - 256;
                int hl = (i2 >= 320);
                int j = i2 - (hl ? 320 : 0);
                int n = j >> 1, half = j & 1;
                const __nv_bfloat16* src =
                    g_WencK + ((size_t)(rel * 2 + hl) * 320 + fs + n) * 320 + k0 + half * 8;
                cpa16(sb + (uint32_t)(18432 + buf * 15360 + hl * 7680 + n * 48 + half * 16), src);
            }
        }
        cpa_commit();
    };

    float C[10][4];
#pragma unroll
    for (int ni = 0; ni < 10; ni++)
#pragma unroll
        for (int q = 0; q < 4; q++) C[ni][q] = 0.f;

    fill(0, 0);
    fill(1, 1);
    for (int t = 0; t < 20; t++) {
        int buf = t % 3;
        if (t < 18) { fill(t + 2, (t + 2) % 3); cpa_wait<2>(); }
        else if (t == 18) { cpa_wait<1>(); }
        else              { cpa_wait<0>(); }
        __syncthreads();

        uint32_t abase = sb + (uint32_t)(buf * 6144) + aoff;
        uint32_t Ah[4], Al[4];
        ldsm4(Ah, abase);
        ldsm4(Al, abase + 3072);
        uint32_t bbase = sb + (uint32_t)(18432 + buf * 15360) + boff;
#pragma unroll
        for (int pair = 0; pair < 5; pair++) {
            uint32_t Bh4[4], Bl4[4];
            ldsm4(Bh4, bbase + pair * 768);
            ldsm4(Bl4, bbase + 7680 + pair * 768);
#pragma unroll
            for (int sub = 0; sub < 2; sub++) {
                int ni = pair * 2 + sub;
                mma_bf16(C[ni], Ah, Bh4 + sub * 2);
                mma_bf16(C[ni], Ah, Bl4 + sub * 2);
                mma_bf16(C[ni], Al, Bh4 + sub * 2);
            }
        }
        __syncthreads();
    }

    int r0 = warp_m * 16 + (lane >> 2);
    int mmA = meta[r0], mmB = meta[r0 + 8];
#pragma unroll
    for (int ni = 0; ni < 10; ni++) {
        int f = fs + warp_n * 80 + ni * 8 + (lane & 3) * 2;
        if (f < 300) {
            if (mmA >= 0)
                *(float2*)(g_t + (size_t)mmA * HSTR + f) = make_float2(C[ni][0], C[ni][1]);
            if (mmB >= 0)
                *(float2*)(g_t + (size_t)mmB * HSTR + f) = make_float2(C[ni][2], C[ni][3]);
        }
    }
}

// ---------------- 5. MLP GEMM: 64x160, double-buffered, k-split slabs ------------
__global__ void __launch_bounds__(256, 3) fc_mma(int sel, int kpad, int nt) {
    __shared__ __align__(16) char smem[43008];
    uint32_t sb = s2u(smem);
    int m0 = blockIdx.x * 64;
    int fs = blockIdx.y * 160;
    int z  = blockIdx.z;
    int kbeg = z * nt * 16;

    const __nv_bfloat16 *Ahi, *Alo, *WB;
    float* acc;
    if (sel == 0)      { Ahi = g_xb;  Alo = g_xb  + 256 * 1824; WB = g_W0B;  acc = g_acc0; }
    else if (sel == 1) { Ahi = g_y0b; Alo = g_y0b + 256 * 640;  WB = g_W12B; acc = g_acc1; }
    else               { Ahi = g_y1b; Alo = g_y1b + 256 * 640;
                         WB = g_W12B + 2 * 600 * 640;            acc = g_acc2; }

    int tid = threadIdx.x, lane = tid & 31, warp = tid >> 5;
    int warp_m = warp >> 1, warp_n = warp & 1;
    uint32_t aoff = (uint32_t)((warp_m * 16 + (lane & 15)) * 48 + (lane >> 4) * 16);
    uint32_t boff = (uint32_t)((warp_n * 80 + ((lane >> 4) << 3) + (lane & 7)) * 48
                               + ((lane >> 3) & 1) * 16);

    auto fill = [&](int c, int buf) {
        int k0 = kbeg + c * 16;
        for (int i = tid; i < 896; i += 256) {
            if (i < 256) {
                int hl = i >> 7, j = i & 127, m = j >> 1, half = j & 1;
                const __nv_bfloat16* src =
                    (hl ? Alo : Ahi) + (size_t)(m0 + m) * kpad + k0 + half * 8;
                cpa16(sb + (uint32_t)(buf * 6144 + hl * 3072 + m * 48 + half * 16), src);
            } else {
                int i2 = i - 256;
                int hl = (i2 >= 320);
                int j = i2 - (hl ? 320 : 0);
                int n = j >> 1, half = j & 1;
                int f = fs + n;
                const void* src = (f < 600)
                    ? (const void*)(WB + ((size_t)hl * 600 + f) * kpad + k0 + half * 8)
                    : (const void*)g_zero;
                cpa16(sb + (uint32_t)(12288 + buf * 15360 + hl * 7680 + n * 48 + half * 16), src);
            }
        }
        cpa_commit();
    };

    float C[10][4];
#pragma unroll
    for (int ni = 0; ni < 10; ni++)
#pragma unroll
        for (int q = 0; q < 4; q++) C[ni][q] = 0.f;

    fill(0, 0);
    for (int t = 0; t < nt; t++) {
        int buf = t & 1;
        if (t < nt - 1) { fill(t + 1, buf ^ 1); cpa_wait<1>(); }
        else            { cpa_wait<0>(); }
        __syncthreads();

        uint32_t abase = sb + (uint32_t)(buf * 6144) + aoff;
        uint32_t Ah[4], Al[4];
        ldsm4(Ah, abase);
        ldsm4(Al, abase + 3072);
        uint32_t bbase = sb + (uint32_t)(12288 + buf * 15360) + boff;
#pragma unroll
        for (int pair = 0; pair < 5; pair++) {
            uint32_t Bh4[4], Bl4[4];
            ldsm4(Bh4, bbase + pair * 768);
            ldsm4(Bl4, bbase + 7680 + pair * 768);
#pragma unroll
            for (int sub = 0; sub < 2; sub++) {
                int ni = pair * 2 + sub;
                mma_bf16(C[ni], Ah, Bh4 + sub * 2);
                mma_bf16(C[ni], Ah, Bl4 + sub * 2);
                mma_bf16(C[ni], Al, Bh4 + sub * 2);
            }
        }
        __syncthreads();
    }

    int row = m0 + warp_m * 16 + (lane >> 2);
#pragma unroll
    for (int ni = 0; ni < 10; ni++) {
        int f = fs + warp_n * 80 + ni * 8 + (lane & 3) * 2;
        if (f < 600) {
            *(float2*)(acc + (size_t)z * 153600 + (size_t)row * 600 + f) =
                make_float2(C[ni][0], C[ni][1]);
            *(float2*)(acc + (size_t)z * 153600 + (size_t)(row + 8) * 600 + f) =
                make_float2(C[ni][2], C[ni][3]);
        }
    }
}

// ---------------- 6. combine (float4) + bf16 mirror refresh ---------------------
__global__ void update_kernel(const int* __restrict__ prel, const int* __restrict__ hrel,
                              int plo) {
    int p = plo + blockIdx.x;
    int b = blockIdx.y, tree = blockIdx.z;
    int e4 = threadIdx.x;
    if (e4 >= 76) return;
    const int* rel = (tree ? hrel : prel) + b * 64;
    size_t rbase = (size_t)(tree * BATCH + b) * NNODE;
    size_t base = rbase * HSTR;
    const float4* hb = (const float4*)(g_h + base);
    const float4* tb = (const float4*)(g_t + base);
    int c0 = 4 * p + 1;
    int c1 = 4 * p + 4; if (c1 > 63) c1 = 63;
    float4 s = make_float4(0.f, 0.f, 0.f, 0.f);
#pragma unroll
    for (int c = c0; c <= c1; c++) {
        if (c > 63) break;
        unsigned rid = (unsigned)rel[c];
        const float4* src = (rid <= 2u) ? tb : hb;
        float4 v = src[c * 76 + e4];
        s.x += v.x; s.y += v.y; s.z += v.z; s.w += v.w;
    }
    float cntf = (float)(c1 - c0 + 1);
    float4 hp = hb[p * 76 + e4];
    float4 o;
    o.x = fmaxf(hp.x * (s.x / cntf), 0.f);
    o.y = fmaxf(hp.y * (s.y / cntf), 0.f);
    o.z = fmaxf(hp.z * (s.z / cntf), 0.f);
    o.w = fmaxf(hp.w * (s.w / cntf), 0.f);
    ((float4*)(g_h + base))[p * 76 + e4] = o;
    __nv_bfloat16* mhi = g_hbhi + (rbase + p) * 320 + 4 * e4;
    __nv_bfloat16* mlo = g_hblo + (rbase + p) * 320 + 4 * e4;
    float vv[4] = {o.x, o.y, o.z, o.w};
#pragma unroll
    for (int q = 0; q < 4; q++) {
        __nv_bfloat16 hi = __float2bfloat16(vv[q]);
        mhi[q] = hi;
        mlo[q] = __float2bfloat16(vv[q] - __bfloat162float(hi));
    }
}

// ---------------- 7. fused root update + MLP input (bf16 hi/lo planes) ----------
__global__ void update1_buildx(const int* __restrict__ prel, const int* __restrict__ hrel) {
    int b = blockIdx.x;
    int e = threadIdx.x;
    __shared__ float root[2][300];
#pragma unroll
    for (int tree = 0; tree < 2; tree++) {
        if (e < 300) {
            const int* rel = (tree ? hrel : prel) + b * 64;
            size_t base = ((size_t)(tree * BATCH + b) * NNODE) * HSTR;
            const float* hb = g_h + base;
            const float* tb = g_t + base;
            float s = 0.f;
#pragma unroll
            for (int c = 1; c <= 4; c++) {
                unsigned rid = (unsigned)rel[c];
                s += (rid <= 2u) ? tb[c * HSTR + e] : hb[c * HSTR + e];
            }
            float v = hb[e] * (s * 0.25f);
            root[tree][e] = fmaxf(v, 0.f);
        }
    }
    __syncthreads();
    if (e >= 300) return;
    float pr = g_rep2[0][b * EMB + e] + g_rep2[1][b * EMB + e];
    float hr = g_rep2[0][(BATCH + b) * EMB + e] + g_rep2[1][(BATCH + b) * EMB + e];
    float ps = root[0][e], hs = root[1][e];
    float vals[6] = {pr, hr, pr - hr, pr * hr, ps - hs, ps * hs};
    __nv_bfloat16* xh = g_xb + (size_t)b * 1824;
    __nv_bfloat16* xl = g_xb + 256 * 1824 + (size_t)b * 1824;
#pragma unroll
    for (int i = 0; i < 6; i++) {
        int col = i * 300 + e;
        __nv_bfloat16 hi = __float2bfloat16(vals[i]);
        xh[col] = hi;
        xl[col] = __float2bfloat16(vals[i] - __bfloat162float(hi));
    }
}

// ---------------- 8. reduce k-split slabs + bias + relu -> bf16 planes ----------
__global__ void bias_relu_kernel(const float* __restrict__ bias, int sel, int nz) {
    int b = blockIdx.x, n = threadIdx.x;
    const float* acc = (sel == 0) ? g_acc0 : g_acc1;
    float s = bias[n];
    for (int z = 0; z < nz; z++) s += acc[(size_t)z * BATCH * 600 + b * 600 + n];
    float v = s > 0.f ? s : 0.f;
    __nv_bfloat16* yh = (sel == 0) ? g_y0b : g_y1b;
    __nv_bfloat16 hi = __float2bfloat16(v);
    yh[(size_t)b * 640 + n] = hi;
    yh[256 * 640 + (size_t)b * 640 + n] = __float2bfloat16(v - __bfloat162float(hi));
}

// ---------------- 9. fused layer-2 reduce + bias + relu + output ----------------
__global__ void bias2_out(const float* __restrict__ bias, const float* __restrict__ Wout,
                          const float* __restrict__ bout, float* __restrict__ out) {
    int b = blockIdx.x, n = threadIdx.x;
    __shared__ float sy[600];
    if (n < 600) {
        float s = bias[n];
        for (int z = 0; z < 10; z++) s += g_acc2[(size_t)z * BATCH * 600 + b * 600 + n];
        sy[n] = s > 0.f ? s : 0.f;
    }
    __syncthreads();
    int w = n >> 5, lane = n & 31;
    if (w >= 3) return;
    float s = 0.f;
    for (int k = lane; k < 600; k += 32)
        s += sy[k] * Wout[w * 600 + k];
    for (int o = 16; o; o >>= 1) s += __shfl_down_sync(0xffffffffu, s, o);
    if (lane == 0) out[b * 3 + w] = s + bout[w];
}

// ---------------- launch ----------------------------------------------------------
extern "C" void kernel_launch(void* const* d_in, const int* in_sizes, int n_in,
                              void* d_out, int out_size) {
    const int*   px   = (const int*)d_in[0];
    const int*   hx   = (const int*)d_in[1];
    const int*   pwi  = (const int*)d_in[2];
    const int*   prel = (const int*)d_in[3];
    const int*   hwi  = (const int*)d_in[4];
    const int*   hrel = (const int*)d_in[5];
    const float* E    = (const float*)d_in[8];
    const float* Wenc = (const float*)d_in[9];
    const float* W0w  = (const float*)d_in[10];
    const float* W0b  = (const float*)d_in[11];
    const float* W1w  = (const float*)d_in[12];
    const float* W1b  = (const float*)d_in[13];
    const float* W2w  = (const float*)d_in[14];
    const float* W2b  = (const float*)d_in[15];
    const float* Wow  = (const float*)d_in[16];
    const float* Wob  = (const float*)d_in[17];
    float* out = (float*)d_out;

    static int smem_set = 0;
    if (!smem_set) {
        cudaFuncSetAttribute(tree_mma, cudaFuncAttributeMaxDynamicSharedMemorySize, TMMA_SMEM);
        smem_set = 1;
    }

    wtrans_fused<<<8086, 256>>>(Wenc, W0w, W1w, W2w);                     // 1 (+zero g_cnt)
    embed_kernel<<<1024, 320>>>(px, hx, pwi, hwi, E);                     // 2
    compact_kernel<<<99, 256>>>(prel, hrel);                              // 3

    tree_mma<<<dim3(344, 2, 3), 256, TMMA_SMEM>>>(2);                     // 4
    update_kernel<<<dim3(11, 256, 2), 96>>>(prel, hrel, 5);               // 5
    tree_mma<<<dim3(128, 2, 3), 256, TMMA_SMEM>>>(1);                     // 6 <- profiled
    update_kernel<<<dim3(4, 256, 2), 96>>>(prel, hrel, 1);                // 7
    tree_mma<<<dim3(32, 2, 3), 256, TMMA_SMEM>>>(0);                      // 8
    update1_buildx<<<256, 320>>>(prel, hrel);                             // 9

    fc_mma<<<dim3(4, 4, 19), 256>>>(0, 1824, 6);                          // 10
    bias_relu_kernel<<<256, 600>>>(W0b, 0, 19);                           // 11
    fc_mma<<<dim3(4, 4, 10), 256>>>(1, 640, 4);                           // 12
    bias_relu_kernel<<<256, 600>>>(W1b, 1, 10);                           // 13
    fc_mma<<<dim3(4, 4, 10), 256>>>(2, 640, 4);                           // 14
    bias2_out<<<256, 608>>>(W2b, Wow, Wob, out);                          // 15
}

// round 13
// speedup vs baseline: 1.1545x; 1.0624x over previous
#include <cuda_runtime.h>
#include <cuda_bf16.h>
#include <cstdint>

#define EMB 300
#define HSTR 304
#define BATCH 256
#define NNODE 64

// ---------------- scratch (static device memory; zero-initialized) -----------
__device__ float g_t[2 * BATCH * NNODE * HSTR];
__device__ __align__(16) __nv_bfloat16 g_hbhi[2 * BATCH * NNODE * 320];
__device__ __align__(16) __nv_bfloat16 g_hblo[2 * BATCH * NNODE * 320];
__device__ __align__(16) __nv_bfloat16 g_WencK[3 * 2 * 320 * 320]; // [rel][hi/lo][f][k]
__device__ __align__(16) __nv_bfloat16 g_W0B[2 * 600 * 1824];      // [hi/lo][f][k]
__device__ __align__(16) __nv_bfloat16 g_W12B[2 * 2 * 600 * 640];  // [ly][hi/lo][f][k]
__device__ __align__(16) __nv_bfloat16 g_xb[2 * 256 * 1824];       // [hi/lo][b][k]
__device__ __align__(16) __nv_bfloat16 g_y0b[2 * 256 * 640];
__device__ __align__(16) __nv_bfloat16 g_y1b[2 * 256 * 640];
__device__ __align__(16) float g_zero[8];                          // stays zero
__device__ float g_rep2[2][2 * BATCH * EMB];                       // rep partials
__device__ float g_acc0[19 * BATCH * 600];
__device__ float g_acc1[10 * BATCH * 600];
__device__ float g_acc2[10 * BATCH * 600];
__device__ int   g_rows[9][22016];
__device__ int   g_cnt[9];

// ---------------- helpers -----------------------------------------------------
__device__ __forceinline__ uint32_t s2u(const void* p) {
    return (uint32_t)__cvta_generic_to_shared(p);
}
__device__ __forceinline__ void cpa16(uint32_t s, const void* g) {
    asm volatile("cp.async.cg.shared.global [%0],[%1],16;" :: "r"(s), "l"(g));
}
__device__ __forceinline__ void cpa_commit() { asm volatile("cp.async.commit_group;"); }
template <int N> __device__ __forceinline__ void cpa_wait() {
    asm volatile("cp.async.wait_group %0;" :: "n"(N));
}
__device__ __forceinline__ void ldsm4(uint32_t* r, uint32_t a) {
    asm volatile("ldmatrix.sync.aligned.m8n8.x4.shared.b16 {%0,%1,%2,%3},[%4];"
        : "=r"(r[0]), "=r"(r[1]), "=r"(r[2]), "=r"(r[3]) : "r"(a));
}
__device__ __forceinline__ void mma_bf16(float* c, const uint32_t* a, const uint32_t* b) {
    asm volatile(
        "mma.sync.aligned.m16n8k16.row.col.f32.bf16.bf16.f32 "
        "{%0,%1,%2,%3},{%4,%5,%6,%7},{%8,%9},{%0,%1,%2,%3};"
        : "+f"(c[0]), "+f"(c[1]), "+f"(c[2]), "+f"(c[3])
        : "r"(a[0]), "r"(a[1]), "r"(a[2]), "r"(a[3]), "r"(b[0]), "r"(b[1]));
}
// read 4 fp32 values reconstructed from bf16 hi/lo mirrors at element offset idx
__device__ __forceinline__ float4 rdmir(const __nv_bfloat16* mhi, const __nv_bfloat16* mlo,
                                        size_t idx) {
    __nv_bfloat162 h0 = *(const __nv_bfloat162*)(mhi + idx);
    __nv_bfloat162 h1 = *(const __nv_bfloat162*)(mhi + idx + 2);
    __nv_bfloat162 l0 = *(const __nv_bfloat162*)(mlo + idx);
    __nv_bfloat162 l1 = *(const __nv_bfloat162*)(mlo + idx + 2);
    float4 r;
    r.x = __bfloat162float(h0.x) + __bfloat162float(l0.x);
    r.y = __bfloat162float(h0.y) + __bfloat162float(l0.y);
    r.z = __bfloat162float(h1.x) + __bfloat162float(l1.x);
    r.w = __bfloat162float(h1.y) + __bfloat162float(l1.y);
    return r;
}

// ---------------- 1. unified weight conversion (Wenc + W0 + W1/W2) -------------
__global__ void wtrans_fused(const float* __restrict__ Wenc, const float* __restrict__ W0,
                             const float* __restrict__ W1, const float* __restrict__ W2) {
    int gi = blockIdx.x * 256 + threadIdx.x;
    if (gi < 9) g_cnt[gi] = 0;
    if (gi < 270000) {                  // Wenc: 3 x 300 x 300
        int rel = gi / 90000;
        int r2 = gi - rel * 90000;
        int f = r2 / 300, k = r2 - f * 300;
        float v = Wenc[gi];
        __nv_bfloat16 hi = __float2bfloat16(v);
        __nv_bfloat16 lo = __float2bfloat16(v - __bfloat162float(hi));
        g_WencK[((size_t)(rel * 2 + 0) * 320 + f) * 320 + k] = hi;
        g_WencK[((size_t)(rel * 2 + 1) * 320 + f) * 320 + k] = lo;
        return;
    }
    gi -= 270000;
    if (gi < 1080000) {                 // W0: 600 x 1800
        int f = gi / 1800, k = gi - f * 1800;
        float v = W0[gi];
        __nv_bfloat16 hi = __float2bfloat16(v);
        __nv_bfloat16 lo = __float2bfloat16(v - __bfloat162float(hi));
        g_W0B[(size_t)f * 1824 + k] = hi;
        g_W0B[(size_t)(600 + f) * 1824 + k] = lo;
        return;
    }
    gi -= 1080000;
    if (gi >= 720000) return;           // W1/W2: 600 x 600 each
    int ly = gi / 360000;
    int r2 = gi - ly * 360000;
    int f = r2 / 600, k = r2 - f * 600;
    float v = (ly ? W2 : W1)[r2];
    __nv_bfloat16 hi = __float2bfloat16(v);
    __nv_bfloat16 lo = __float2bfloat16(v - __bfloat162float(hi));
    size_t base = (size_t)ly * 2 * 600 * 640;
    g_W12B[base + (size_t)f * 640 + k] = hi;
    g_W12B[base + (size_t)(600 + f) * 640 + k] = lo;
}

// ---------------- 2. embeddings: mirrors only (no fp32 h state) -----------------
__global__ void embed_kernel(const int* __restrict__ px, const int* __restrict__ hx,
                             const int* __restrict__ pwi, const int* __restrict__ hwi,
                             const float* __restrict__ E) {
    __shared__ int sx[64], swi[64];
    int tid = threadIdx.x;
    int half = blockIdx.x & 1;
    int b = (blockIdx.x >> 1) & 255;
    int tree = blockIdx.x >> 9;
    const int* x  = (tree ? hx : px) + b * 64;
    const int* wi = (tree ? hwi : pwi) + b * 64;
    if (tid < 64) { sx[tid] = x[tid]; swi[tid] = wi[tid]; }
    __syncthreads();
    size_t row0 = (size_t)(tree * BATCH + b) * NNODE;
    __nv_bfloat16* mhi = g_hbhi + row0 * 320;
    __nv_bfloat16* mlo = g_hblo + row0 * 320;
    int n0 = half * 32;
    if (tid >= 300) {
        __nv_bfloat16 z = __float2bfloat16(0.f);
        for (int n = n0; n < n0 + 32; n++) {
            mhi[n * 320 + tid] = z;
            mlo[n * 320 + tid] = z;
        }
        return;
    }
    float rep = 0.f;
#pragma unroll 8
    for (int s = n0; s < n0 + 32; s++) rep += __ldg(&E[(size_t)sx[s] * EMB + tid]);
    g_rep2[half][((size_t)tree * BATCH + b) * EMB + tid] = rep;
    for (int n = n0; n < n0 + 32; n++) {
        int w = swi[n];
        float v = (w < 0) ? 1.0f : __ldg(&E[(size_t)sx[w] * EMB + tid]);
        __nv_bfloat16 hi = __float2bfloat16(v);
        mhi[n * 320 + tid] = hi;
        mlo[n * 320 + tid] = __float2bfloat16(v - __bfloat162float(hi));
    }
}

// ---------------- 3. compaction per (level, rel) --------------------------------
__global__ void compact_kernel(const int* __restrict__ prel, const int* __restrict__ hrel) {
    __shared__ unsigned ball[64];
    __shared__ int pref[64];
    __shared__ int sbase;
    int tid = threadIdx.x, lane = tid & 31, wid = tid >> 5;
    int cb = blockIdx.x;
    int li = cb % 9, chunk = cb / 9;
    int l = li / 3, r = li % 3;
    int n0, nc;
    if (l == 0)      { n0 = 1;  nc = 4;  }
    else if (l == 1) { n0 = 5;  nc = 16; }
    else             { n0 = 21; nc = 43; }
    int total = 512 * nc;
    int base = chunk * 2048;
    if (base >= total) return;
#pragma unroll
    for (int it = 0; it < 8; it++) {
        int i = base + it * 256 + tid;
        int flag = 0;
        if (i < total) {
            int tb = i / nc;
            int n = n0 + (i - tb * nc);
            int tree = tb >> 8, b = tb & 255;
            flag = ((tree ? hrel : prel)[b * 64 + n] == r);
        }
        unsigned m = __ballot_sync(0xffffffffu, flag);
        if (lane == 0) ball[wid * 8 + it] = m;
    }
    __syncthreads();
    if (tid == 0) {
        int run = 0;
        for (int s = 0; s < 64; s++) { pref[s] = run; run += __popc(ball[s]); }
        sbase = atomicAdd(&g_cnt[li], run);
    }
    __syncthreads();
#pragma unroll
    for (int it = 0; it < 8; it++) {
        int i = base + it * 256 + tid;
        int flag = 0, v = 0;
        if (i < total) {
            int tb = i / nc;
            int n = n0 + (i - tb * nc);
            int tree = tb >> 8, b = tb & 255;
            flag = ((tree ? hrel : prel)[b * 64 + n] == r);
            v = (tb << 6) | n;
        }
        unsigned m = ball[wid * 8 + it];
        int within = __popc(m & ((1u << lane) - 1));
        if (flag) g_rows[li][sbase + pref[wid * 8 + it] + within] = v;
    }
}

// ---------------- 4. tree GEMM: 64x160, 3xBF16, triple-buffered ------------------
// dyn smem: A[3][2][64][48B]=18432, B[3][2][160][48B]=46080 -> 64512
#define TMMA_SMEM 64512
__global__ void __launch_bounds__(256, 3) tree_mma(int l) {
    extern __shared__ __align__(16) char smem[];
    __shared__ int meta[64];
    int rel = blockIdx.z;
    int li = l * 3 + rel;
    int cnt = g_cnt[li];
    int row0 = blockIdx.x * 64;
    if (row0 >= cnt) return;
    int fs = blockIdx.y * 160;

    uint32_t sb = s2u(smem);
    int tid = threadIdx.x, lane = tid & 31, warp = tid >> 5;
    int warp_m = warp >> 1, warp_n = warp & 1;
    if (tid < 64) {
        int rr = row0 + tid;
        meta[tid] = (rr < cnt) ? g_rows[li][rr] : -1;
    }
    __syncthreads();

    uint32_t aoff = (uint32_t)((warp_m * 16 + (lane & 15)) * 48 + (lane >> 4) * 16);
    uint32_t boff = (uint32_t)((warp_n * 80 + ((lane >> 4) << 3) + (lane & 7)) * 48
                               + ((lane >> 3) & 1) * 16);

    auto fill = [&](int c, int buf) {
        int k0 = c * 16;
        for (int i = tid; i < 896; i += 256) {
            if (i < 256) {
                int hl = i >> 7, j = i & 127, m = j >> 1, half = j & 1;
                int mm = meta[m];
                const void* src = (mm < 0) ? (const void*)g_zero
                    : (const void*)((hl ? g_hblo : g_hbhi) + (size_t)mm * 320 + k0 + half * 8);
                cpa16(sb + (uint32_t)(buf * 6144 + hl * 3072 + m * 48 + half * 16), src);
            } else {
                int i2 = i - 256;
                int hl = (i2 >= 320);
                int j = i2 - (hl ? 320 : 0);
                int n = j >> 1, half = j & 1;
                const __nv_bfloat16* src =
                    g_WencK + ((size_t)(rel * 2 + hl) * 320 + fs + n) * 320 + k0 + half * 8;
                cpa16(sb + (uint32_t)(18432 + buf * 15360 + hl * 7680 + n * 48 + half * 16), src);
            }
        }
        cpa_commit();
    };

    float C[10][4];
#pragma unroll
    for (int ni = 0; ni < 10; ni++)
#pragma unroll
        for (int q = 0; q < 4; q++) C[ni][q] = 0.f;

    fill(0, 0);
    fill(1, 1);
    for (int t = 0; t < 20; t++) {
        int buf = t % 3;
        if (t < 18) { fill(t + 2, (t + 2) % 3); cpa_wait<2>(); }
        else if (t == 18) { cpa_wait<1>(); }
        else              { cpa_wait<0>(); }
        __syncthreads();

        uint32_t abase = sb + (uint32_t)(buf * 6144) + aoff;
        uint32_t Ah[4], Al[4];
        ldsm4(Ah, abase);
        ldsm4(Al, abase + 3072);
        uint32_t bbase = sb + (uint32_t)(18432 + buf * 15360) + boff;
#pragma unroll
        for (int pair = 0; pair < 5; pair++) {
            uint32_t Bh4[4], Bl4[4];
            ldsm4(Bh4, bbase + pair * 768);
            ldsm4(Bl4, bbase + 7680 + pair * 768);
#pragma unroll
            for (int sub = 0; sub < 2; sub++) {
                int ni = pair * 2 + sub;
                mma_bf16(C[ni], Ah, Bh4 + sub * 2);
                mma_bf16(C[ni], Ah, Bl4 + sub * 2);
                mma_bf16(C[ni], Al, Bh4 + sub * 2);
            }
        }
        __syncthreads();
    }

    int r0 = warp_m * 16 + (lane >> 2);
    int mmA = meta[r0], mmB = meta[r0 + 8];
#pragma unroll
    for (int ni = 0; ni < 10; ni++) {
        int f = fs + warp_n * 80 + ni * 8 + (lane & 3) * 2;
        if (f < 300) {
            if (mmA >= 0)
                *(float2*)(g_t + (size_t)mmA * HSTR + f) = make_float2(C[ni][0], C[ni][1]);
            if (mmB >= 0)
                *(float2*)(g_t + (size_t)mmB * HSTR + f) = make_float2(C[ni][2], C[ni][3]);
        }
    }
}

// ---------------- 5. MLP GEMM: 64x160, double-buffered, k-split slabs ------------
__global__ void __launch_bounds__(256, 3) fc_mma(int sel, int kpad, int nt) {
    __shared__ __align__(16) char smem[43008];
    uint32_t sb = s2u(smem);
    int m0 = blockIdx.x * 64;
    int fs = blockIdx.y * 160;
    int z  = blockIdx.z;
    int kbeg = z * nt * 16;

    const __nv_bfloat16 *Ahi, *Alo, *WB;
    float* acc;
    if (sel == 0)      { Ahi = g_xb;  Alo = g_xb  + 256 * 1824; WB = g_W0B;  acc = g_acc0; }
    else if (sel == 1) { Ahi = g_y0b; Alo = g_y0b + 256 * 640;  WB = g_W12B; acc = g_acc1; }
    else               { Ahi = g_y1b; Alo = g_y1b + 256 * 640;
                         WB = g_W12B + 2 * 600 * 640;            acc = g_acc2; }

    int tid = threadIdx.x, lane = tid & 31, warp = tid >> 5;
    int warp_m = warp >> 1, warp_n = warp & 1;
    uint32_t aoff = (uint32_t)((warp_m * 16 + (lane & 15)) * 48 + (lane >> 4) * 16);
    uint32_t boff = (uint32_t)((warp_n * 80 + ((lane >> 4) << 3) + (lane & 7)) * 48
                               + ((lane >> 3) & 1) * 16);

    auto fill = [&](int c, int buf) {
        int k0 = kbeg + c * 16;
        for (int i = tid; i < 896; i += 256) {
            if (i < 256) {
                int hl = i >> 7, j = i & 127, m = j >> 1, half = j & 1;
                const __nv_bfloat16* src =
                    (hl ? Alo : Ahi) + (size_t)(m0 + m) * kpad + k0 + half * 8;
                cpa16(sb + (uint32_t)(buf * 6144 + hl * 3072 + m * 48 + half * 16), src);
            } else {
                int i2 = i - 256;
                int hl = (i2 >= 320);
                int j = i2 - (hl ? 320 : 0);
                int n = j >> 1, half = j & 1;
                int f = fs + n;
                const void* src = (f < 600)
                    ? (const void*)(WB + ((size_t)hl * 600 + f) * kpad + k0 + half * 8)
                    : (const void*)g_zero;
                cpa16(sb + (uint32_t)(12288 + buf * 15360 + hl * 7680 + n * 48 + half * 16), src);
            }
        }
        cpa_commit();
    };

    float C[10][4];
#pragma unroll
    for (int ni = 0; ni < 10; ni++)
#pragma unroll
        for (int q = 0; q < 4; q++) C[ni][q] = 0.f;

    fill(0, 0);
    for (int t = 0; t < nt; t++) {
        int buf = t & 1;
        if (t < nt - 1) { fill(t + 1, buf ^ 1); cpa_wait<1>(); }
        else            { cpa_wait<0>(); }
        __syncthreads();

        uint32_t abase = sb + (uint32_t)(buf * 6144) + aoff;
        uint32_t Ah[4], Al[4];
        ldsm4(Ah, abase);
        ldsm4(Al, abase + 3072);
        uint32_t bbase = sb + (uint32_t)(12288 + buf * 15360) + boff;
#pragma unroll
        for (int pair = 0; pair < 5; pair++) {
            uint32_t Bh4[4], Bl4[4];
            ldsm4(Bh4, bbase + pair * 768);
            ldsm4(Bl4, bbase + 7680 + pair * 768);
#pragma unroll
            for (int sub = 0; sub < 2; sub++) {
                int ni = pair * 2 + sub;
                mma_bf16(C[ni], Ah, Bh4 + sub * 2);
                mma_bf16(C[ni], Ah, Bl4 + sub * 2);
                mma_bf16(C[ni], Al, Bh4 + sub * 2);
            }
        }
        __syncthreads();
    }

    int row = m0 + warp_m * 16 + (lane >> 2);
#pragma unroll
    for (int ni = 0; ni < 10; ni++) {
        int f = fs + warp_n * 80 + ni * 8 + (lane & 3) * 2;
        if (f < 600) {
            *(float2*)(acc + (size_t)z * 153600 + (size_t)row * 600 + f) =
                make_float2(C[ni][0], C[ni][1]);
            *(float2*)(acc + (size_t)z * 153600 + (size_t)(row + 8) * 600 + f) =
                make_float2(C[ni][2], C[ni][3]);
        }
    }
}

// ---------------- 6. combine: mirrors in, mirrors out ----------------------------
__global__ void update_kernel(const int* __restrict__ prel, const int* __restrict__ hrel,
                              int plo) {
    int p = plo + blockIdx.x;
    int b = blockIdx.y, tree = blockIdx.z;
    int e4 = threadIdx.x;
    if (e4 >= 76) return;
    const int* rel = (tree ? hrel : prel) + b * 64;
    size_t rbase = (size_t)(tree * BATCH + b) * NNODE;
    const float4* tb = (const float4*)(g_t + rbase * HSTR);
    __nv_bfloat16* mhi = g_hbhi + rbase * 320;
    __nv_bfloat16* mlo = g_hblo + rbase * 320;
    int c0 = 4 * p + 1;
    int c1 = 4 * p + 4; if (c1 > 63) c1 = 63;
    float4 s = make_float4(0.f, 0.f, 0.f, 0.f);
#pragma unroll
    for (int c = c0; c <= c1; c++) {
        if (c > 63) break;
        unsigned rid = (unsigned)rel[c];
        float4 v = (rid <= 2u) ? tb[c * 76 + e4]
                               : rdmir(mhi, mlo, (size_t)c * 320 + 4 * e4);
        s.x += v.x; s.y += v.y; s.z += v.z; s.w += v.w;
    }
    float inv = 1.0f / (float)(c1 - c0 + 1);
    float4 hp = rdmir(mhi, mlo, (size_t)p * 320 + 4 * e4);
    float vv[4];
    vv[0] = fmaxf(hp.x * (s.x * inv), 0.f);
    vv[1] = fmaxf(hp.y * (s.y * inv), 0.f);
    vv[2] = fmaxf(hp.z * (s.z * inv), 0.f);
    vv[3] = fmaxf(hp.w * (s.w * inv), 0.f);
    __nv_bfloat16* wh = mhi + (size_t)p * 320 + 4 * e4;
    __nv_bfloat16* wl = mlo + (size_t)p * 320 + 4 * e4;
#pragma unroll
    for (int q = 0; q < 4; q++) {
        __nv_bfloat16 hi = __float2bfloat16(vv[q]);
        wh[q] = hi;
        wl[q] = __float2bfloat16(vv[q] - __bfloat162float(hi));
    }
}

// ---------------- 7. fused root update + MLP input (bf16 hi/lo planes) ----------
__global__ void update1_buildx(const int* __restrict__ prel, const int* __restrict__ hrel) {
    int b = blockIdx.x;
    int e = threadIdx.x;
    __shared__ float root[2][300];
#pragma unroll
    for (int tree = 0; tree < 2; tree++) {
        if (e < 300) {
            const int* rel = (tree ? hrel : prel) + b * 64;
            size_t rbase = (size_t)(tree * BATCH + b) * NNODE;
            const float* tb = g_t + rbase * HSTR;
            const __nv_bfloat16* mhi = g_hbhi + rbase * 320;
            const __nv_bfloat16* mlo = g_hblo + rbase * 320;
            float s = 0.f;
#pragma unroll
            for (int c = 1; c <= 4; c++) {
                unsigned rid = (unsigned)rel[c];
                float v;
                if (rid <= 2u) v = tb[c * HSTR + e];
                else v = __bfloat162float(mhi[c * 320 + e]) + __bfloat162float(mlo[c * 320 + e]);
                s += v;
            }
            float h0 = __bfloat162float(mhi[e]) + __bfloat162float(mlo[e]);
            float v = h0 * (s * 0.25f);
            root[tree][e] = fmaxf(v, 0.f);
        }
    }
    __syncthreads();
    if (e >= 300) return;
    float pr = g_rep2[0][b * EMB + e] + g_rep2[1][b * EMB + e];
    float hr = g_rep2[0][(BATCH + b) * EMB + e] + g_rep2[1][(BATCH + b) * EMB + e];
    float ps = root[0][e], hs = root[1][e];
    float vals[6] = {pr, hr, pr - hr, pr * hr, ps - hs, ps * hs};
    __nv_bfloat16* xh = g_xb + (size_t)b * 1824;
    __nv_bfloat16* xl = g_xb + 256 * 1824 + (size_t)b * 1824;
#pragma unroll
    for (int i = 0; i < 6; i++) {
        int col = i * 300 + e;
        __nv_bfloat16 hi = __float2bfloat16(vals[i]);
        xh[col] = hi;
        xl[col] = __float2bfloat16(vals[i] - __bfloat162float(hi));
    }
}

// ---------------- 8. reduce k-split slabs + bias + relu -> bf16 planes ----------
__global__ void bias_relu_kernel(const float* __restrict__ bias, int sel, int nz) {
    int b = blockIdx.x, n = threadIdx.x;
    const float* acc = (sel == 0) ? g_acc0 : g_acc1;
    float s = bias[n];
    for (int z = 0; z < nz; z++) s += acc[(size_t)z * BATCH * 600 + b * 600 + n];
    float v = s > 0.f ? s : 0.f;
    __nv_bfloat16* yh = (sel == 0) ? g_y0b : g_y1b;
    __nv_bfloat16 hi = __float2bfloat16(v);
    yh[(size_t)b * 640 + n] = hi;
    yh[256 * 640 + (size_t)b * 640 + n] = __float2bfloat16(v - __bfloat162float(hi));
}

// ---------------- 9. fused layer-2 reduce + bias + relu + output ----------------
__global__ void bias2_out(const float* __restrict__ bias, const float* __restrict__ Wout,
                          const float* __restrict__ bout, float* __restrict__ out) {
    int b = blockIdx.x, n = threadIdx.x;
    __shared__ float sy[600];
    if (n < 600) {
        float s = bias[n];
        for (int z = 0; z < 10; z++) s += g_acc2[(size_t)z * BATCH * 600 + b * 600 + n];
        sy[n] = s > 0.f ? s : 0.f;
    }
    __syncthreads();
    int w = n >> 5, lane = n & 31;
    if (w >= 3) return;
    float s = 0.f;
    for (int k = lane; k < 600; k += 32)
        s += sy[k] * Wout[w * 600 + k];
    for (int o = 16; o; o >>= 1) s += __shfl_down_sync(0xffffffffu, s, o);
    if (lane == 0) out[b * 3 + w] = s + bout[w];
}

// ---------------- launch ----------------------------------------------------------
extern "C" void kernel_launch(void* const* d_in, const int* in_sizes, int n_in,
                              void* d_out, int out_size) {
    const int*   px   = (const int*)d_in[0];
    const int*   hx   = (const int*)d_in[1];
    const int*   pwi  = (const int*)d_in[2];
    const int*   prel = (const int*)d_in[3];
    const int*   hwi  = (const int*)d_in[4];
    const int*   hrel = (const int*)d_in[5];
    const float* E    = (const float*)d_in[8];
    const float* Wenc = (const float*)d_in[9];
    const float* W0w  = (const float*)d_in[10];
    const float* W0b  = (const float*)d_in[11];
    const float* W1w  = (const float*)d_in[12];
    const float* W1b  = (const float*)d_in[13];
    const float* W2w  = (const float*)d_in[14];
    const float* W2b  = (const float*)d_in[15];
    const float* Wow  = (const float*)d_in[16];
    const float* Wob  = (const float*)d_in[17];
    float* out = (float*)d_out;

    static int smem_set = 0;
    if (!smem_set) {
        cudaFuncSetAttribute(tree_mma, cudaFuncAttributeMaxDynamicSharedMemorySize, TMMA_SMEM);
        smem_set = 1;
    }

    wtrans_fused<<<8086, 256>>>(Wenc, W0w, W1w, W2w);                     // 1 (+zero g_cnt)
    embed_kernel<<<1024, 320>>>(px, hx, pwi, hwi, E);                     // 2
    compact_kernel<<<99, 256>>>(prel, hrel);                              // 3

    tree_mma<<<dim3(344, 2, 3), 256, TMMA_SMEM>>>(2);                     // 4
    update_kernel<<<dim3(11, 256, 2), 96>>>(prel, hrel, 5);               // 5
    tree_mma<<<dim3(128, 2, 3), 256, TMMA_SMEM>>>(1);                     // 6 <- profiled
    update_kernel<<<dim3(4, 256, 2), 96>>>(prel, hrel, 1);                // 7
    tree_mma<<<dim3(32, 2, 3), 256, TMMA_SMEM>>>(0);                      // 8
    update1_buildx<<<256, 320>>>(prel, hrel);                             // 9

    fc_mma<<<dim3(4, 4, 19), 256>>>(0, 1824, 6);                          // 10
    bias_relu_kernel<<<256, 600>>>(W0b, 0, 19);                           // 11
    fc_mma<<<dim3(4, 4, 10), 256>>>(1, 640, 4);                           // 12
    bias_relu_kernel<<<256, 600>>>(W1b, 1, 10);                           // 13
    fc_mma<<<dim3(4, 4, 10), 256>>>(2, 640, 4);                           // 14
    bias2_out<<<256, 608>>>(W2b, Wow, Wob, out);                          // 15
}